// round 4
// baseline (speedup 1.0000x reference)
#include <cuda_runtime.h>
#include <cstdint>

// Problem constants
#define D_MODEL 192
#define D_INNER 384
#define D_STATE 16
#define DT_RANK 12
#define BB 2
#define HH 64
#define WW 64
#define LL 4096            // HH*WW
#define MM (BB*LL)         // 8192 rows
#define GG (BB*D_INNER)    // 768 sequences
#define NC 32              // chunks per sequence
#define CL (LL/NC)         // 128 steps per chunk

// ---------------- scratch ----------------
__device__ float  g_xa   [MM*D_INNER];
__device__ float  g_z    [MM*D_INNER];
__device__ float  g_c    [MM*D_INNER];
__device__ float  g_u    [MM*D_INNER];
__device__ float  g_s    [MM*D_INNER];
__device__ float4 g_f4   [MM*D_INNER];   // (delta, delta*u, u*D, 0) in scan order
__device__ float  g_bc   [MM*32];        // B(0..15), C(16..31) in scan order
__device__ float  g_y    [MM*D_INNER];   // scan output, SCAN order
__device__ float  g_g    [MM*D_INNER];   // post-LN*z, ORIGINAL order
// chunk summaries
__device__ float g_hF[GG*NC*16];
__device__ float g_P [GG*NC*16];
__device__ float g_hI[GG*NC*16];

__device__ __forceinline__ float silu_f(float x) { return x / (1.f + __expf(-x)); }
__device__ __forceinline__ float softplus_f(float x) {
    return fmaxf(x, 0.f) + log1pf(__expf(-fabsf(x)));
}

// ---------------- K1: fused input GEMMs ----------------
__global__ __launch_bounds__(256) void k1_gemm(
    const float* __restrict__ x, const float* __restrict__ cond,
    const float* __restrict__ Win, const float* __restrict__ Wcon)
{
    __shared__ float As[16][68];
    __shared__ float Ws[16][68];
    const int n0 = blockIdx.x * 64;
    const int m0 = blockIdx.y * 64;
    const int tid = threadIdx.x;
    const bool is_c = (n0 >= 768);
    const float* A = is_c ? cond : x;
    const float* W = is_c ? (Wcon + (size_t)(n0 - 768) * D_MODEL)
                          : (Win  + (size_t)n0 * D_MODEL);
    const int K = D_MODEL;
    const int tx = tid & 15, ty = tid >> 4;
    const int ml = tid >> 2, kl = (tid & 3) * 4;
    float acc[4][4] = {};

    for (int k0 = 0; k0 < K; k0 += 16) {
        float4 a4 = *(const float4*)&A[(size_t)(m0 + ml) * K + k0 + kl];
        float4 w4 = *(const float4*)&W[(size_t)ml * K + k0 + kl];
        __syncthreads();
        As[kl+0][ml] = a4.x; As[kl+1][ml] = a4.y; As[kl+2][ml] = a4.z; As[kl+3][ml] = a4.w;
        Ws[kl+0][ml] = w4.x; Ws[kl+1][ml] = w4.y; Ws[kl+2][ml] = w4.z; Ws[kl+3][ml] = w4.w;
        __syncthreads();
        #pragma unroll
        for (int kk = 0; kk < 16; kk++) {
            float4 av = *(const float4*)&As[kk][ty*4];
            float4 bv = *(const float4*)&Ws[kk][tx*4];
            float a[4] = {av.x, av.y, av.z, av.w};
            float b[4] = {bv.x, bv.y, bv.z, bv.w};
            #pragma unroll
            for (int i = 0; i < 4; i++)
                #pragma unroll
                for (int j = 0; j < 4; j++)
                    acc[i][j] += a[i] * b[j];
        }
    }
    #pragma unroll
    for (int i = 0; i < 4; i++) {
        int m = m0 + ty*4 + i;
        #pragma unroll
        for (int j = 0; j < 4; j++) {
            int n = n0 + tx*4 + j;
            float v = acc[i][j];
            if (n < 384)       g_xa[m*D_INNER + n] = v;
            else if (n < 768)  g_z [m*D_INNER + (n-384)] = silu_f(v);
            else               g_c [m*D_INNER + (n-768)] = v;
        }
    }
}

// ---------------- K2: depthwise 3x3 conv + bias + silu, 4-pixel register tile ----------------
__global__ __launch_bounds__(384) void k2_conv(
    const float* __restrict__ cw, const float* __restrict__ cb,
    const float* __restrict__ ccw, const float* __restrict__ ccb)
{
    const int mb = blockIdx.x * 4;           // 4 consecutive pixels, same row
    const int d  = threadIdx.x;
    const int b = mb >> 12, rem = mb & 4095, h = rem >> 6, w0 = rem & 63;

    float wx[9], wc[9];
    #pragma unroll
    for (int k = 0; k < 9; k++) { wx[k] = __ldg(&cw[d*9+k]); wc[k] = __ldg(&ccw[d*9+k]); }

    float ix[3][6], ic[3][6];
    #pragma unroll
    for (int r = 0; r < 3; r++) {
        int hh = h - 1 + r;
        bool hv = (hh >= 0 && hh < HH);
        #pragma unroll
        for (int c = 0; c < 6; c++) {
            int ww = w0 - 1 + c;
            bool v = hv && (ww >= 0 && ww < WW);
            if (v) {
                int mi = ((b << 12) + (hh << 6) + ww) * D_INNER + d;
                ix[r][c] = g_xa[mi];
                ic[r][c] = g_c[mi];
            } else { ix[r][c] = 0.f; ic[r][c] = 0.f; }
        }
    }
    const float bx = __ldg(&cb[d]), bc2 = __ldg(&ccb[d]);
    #pragma unroll
    for (int px = 0; px < 4; px++) {
        float sx = bx, sc = bc2;
        #pragma unroll
        for (int r = 0; r < 3; r++)
            #pragma unroll
            for (int c = 0; c < 3; c++) {
                sx += ix[r][px + c] * wx[r*3 + c];
                sc += ic[r][px + c] * wc[r*3 + c];
            }
        float uv = silu_f(sx);
        float cv = silu_f(sc);
        int m = mb + px;
        g_u[m*D_INNER + d] = uv;
        g_s[m*D_INNER + d] = uv + cv;
    }
}

// ---------------- K3: tiled gather + x_dbl + (delta, delta*u, u*D) + B/C ----------------
#define R3 16
__global__ __launch_bounds__(384) void k3_proj(
    const float* __restrict__ xpw,   // [44,384]
    const float* __restrict__ dtw,   // [384,12]
    const float* __restrict__ dtb,   // [384]
    const float* __restrict__ Ds,    // [384]
    const int*   __restrict__ perm)  // [4096]
{
    __shared__ float sv[R3][D_INNER];
    __shared__ float xd[R3][48];
    __shared__ int   sp[R3];
    const int r0 = blockIdx.x * R3;     // base scan row (over MM)
    const int t = threadIdx.x;

    if (t < R3) sp[t] = __ldg(perm + ((r0 + t) & 4095));
    __syncthreads();

    // stage 1: gather rows of s into smem
    #pragma unroll
    for (int r = 0; r < R3; r++) {
        int ml = r0 + r;
        int b = ml >> 12;
        sv[r][t] = __ldg(&g_s[((size_t)((b << 12) + sp[r])) * D_INNER + t]);
    }
    __syncthreads();

    // stage 2: x_dbl = sv @ xpw^T  -> xd[16][44]
    #pragma unroll
    for (int pass = 0; pass < 2; pass++) {
        int e = t + pass * 384;
        if (e < R3 * 44) {
            int row = e / 44, c = e % 44;
            const float4* wv = (const float4*)(xpw + (size_t)c * D_INNER);
            const float4* s4 = (const float4*)(&sv[row][0]);
            float a = 0.f;
            #pragma unroll
            for (int k = 0; k < D_INNER/4; k++) {
                float4 w4 = __ldg(&wv[k]);
                float4 s_ = s4[k];
                a += w4.x*s_.x + w4.y*s_.y + w4.z*s_.z + w4.w*s_.w;
            }
            xd[row][c] = a;
        }
    }
    __syncthreads();

    // stage 3: delta, delta*u, u*D  (thread t = channel d)
    {
        float wreg[DT_RANK];
        #pragma unroll
        for (int j = 0; j < DT_RANK; j++) wreg[j] = __ldg(&dtw[t * DT_RANK + j]);
        const float bias = __ldg(&dtb[t]);
        const float Dd = __ldg(&Ds[t]);
        #pragma unroll
        for (int r = 0; r < R3; r++) {
            float acc = bias;
            #pragma unroll
            for (int j = 0; j < DT_RANK; j++) acc += xd[r][j] * wreg[j];
            float de = softplus_f(acc);
            int ml = r0 + r;
            int b = ml >> 12;
            float u = __ldg(&g_u[((size_t)((b << 12) + sp[r])) * D_INNER + t]);
            g_f4[(size_t)ml * D_INNER + t] = make_float4(de, de * u, u * Dd, 0.f);
        }
    }

    // stage 4: B/C out
    for (int idx = t; idx < R3 * 32; idx += 384) {
        int r = idx >> 5, j = idx & 31;
        g_bc[(size_t)(r0 + r) * 32 + j] = xd[r][12 + j];
    }
}

// ---------------- K4a: chunk scan (h0=0), packed: lanes 0-15 = b0, 16-31 = b1 ----------------
__global__ __launch_bounds__(256) void k4a(const float* __restrict__ Alogs)
{
    const int w = blockIdx.x * 8 + (threadIdx.x >> 5);   // w in [0, NC*D_INNER)
    const int lane = threadIdx.x & 31;
    const int chunk = w / D_INNER;
    const int d = w % D_INNER;
    const int half = lane >> 4, sl = lane & 15;
    const float Al = -__expf(__ldg(&Alogs[d * 16 + sl]));

    const int l0 = chunk * CL;
    const float2* f2P = (const float2*)g_f4;   // (delta, delta*u) = first 8B of float4
    const size_t rowBase = (size_t)(half * LL + l0);

    float h = 0.f, P = 1.f;
    #pragma unroll 4
    for (int l = 0; l < CL; l++) {
        float2 f = __ldg(&f2P[((rowBase + l) * D_INNER + d) * 2]);
        float Bv = __ldg(&g_bc[(rowBase + l) * 32 + sl]);
        float a  = __expf(f.x * Al);
        h = a * h + f.y * Bv;
        P *= a;
    }
    const int g = half * D_INNER + d;
    g_hF[(g * NC + chunk) * 16 + sl] = h;
    g_P [(g * NC + chunk) * 16 + sl] = P;
}

// ---------------- K4b: serial combine over chunk summaries ----------------
__global__ __launch_bounds__(256) void k4b()
{
    const int g = blockIdx.x * 8 + (threadIdx.x >> 5);
    const int lane = threadIdx.x & 31;
    if (lane < 16) {
        float h = 0.f;
        #pragma unroll
        for (int c = 0; c < NC; c++) {
            int i = (g * NC + c) * 16 + lane;
            g_hI[i] = h;
            h = g_P[i] * h + g_hF[i];
        }
    }
}

// ---------------- K4c: final chunk scan, packed halves, y in scan order ----------------
__global__ __launch_bounds__(256) void k4c(const float* __restrict__ Alogs)
{
    const int w = blockIdx.x * 8 + (threadIdx.x >> 5);
    const int lane = threadIdx.x & 31;
    const int chunk = w / D_INNER;
    const int d = w % D_INNER;
    const int half = lane >> 4, sl = lane & 15;
    const float Al = -__expf(__ldg(&Alogs[d * 16 + sl]));

    const int l0 = chunk * CL;
    const size_t rowBase = (size_t)(half * LL + l0);
    const int g = half * D_INNER + d;

    float h = g_hI[(g * NC + chunk) * 16 + sl];

    for (int l4 = 0; l4 < CL; l4 += 4) {
        float pr[4], ud[4];
        #pragma unroll
        for (int j = 0; j < 4; j++) {
            int l = l4 + j;
            float4 f = __ldg(&g_f4[(rowBase + l) * D_INNER + d]);
            float Bv = __ldg(&g_bc[(rowBase + l) * 32 + sl]);
            float Cv = __ldg(&g_bc[(rowBase + l) * 32 + 16 + sl]);
            float a  = __expf(f.x * Al);
            h = a * h + f.y * Bv;
            pr[j] = h * Cv;
            ud[j] = f.z;
        }
        #pragma unroll
        for (int j = 0; j < 4; j++) {
            float s = pr[j];
            s += __shfl_xor_sync(0xffffffffu, s, 8);
            s += __shfl_xor_sync(0xffffffffu, s, 4);
            s += __shfl_xor_sync(0xffffffffu, s, 2);
            s += __shfl_xor_sync(0xffffffffu, s, 1);
            if (sl == 0)
                g_y[(rowBase + l4 + j) * D_INNER + d] = s + ud[j];
        }
    }
}

// ---------------- K5: LayerNorm (scan order in) * silu(z), un-permute on write ----------------
__global__ __launch_bounds__(384) void k5_ln(
    const float* __restrict__ lnw, const float* __restrict__ lnb,
    const int* __restrict__ perm)
{
    __shared__ float red0[12], red1[12];
    const int m = blockIdx.x, t = threadIdx.x;   // m = scan row (b*LL + l)
    float v = g_y[(size_t)m * D_INNER + t];
    float s = v, s2 = v * v;
    #pragma unroll
    for (int o = 16; o; o >>= 1) {
        s  += __shfl_xor_sync(0xffffffffu, s,  o);
        s2 += __shfl_xor_sync(0xffffffffu, s2, o);
    }
    if ((t & 31) == 0) { red0[t >> 5] = s; red1[t >> 5] = s2; }
    __syncthreads();
    if (t < 32) {
        float a = (t < 12) ? red0[t] : 0.f;
        float c = (t < 12) ? red1[t] : 0.f;
        #pragma unroll
        for (int o = 16; o; o >>= 1) {
            a += __shfl_xor_sync(0xffffffffu, a, o);
            c += __shfl_xor_sync(0xffffffffu, c, o);
        }
        if (t == 0) { red0[0] = a; red1[0] = c; }
    }
    __syncthreads();
    const float mu  = red0[0] * (1.f / D_INNER);
    const float var = red1[0] * (1.f / D_INNER) - mu * mu;
    const float r = rsqrtf(var + 1e-5f);
    float out = (v - mu) * r * __ldg(&lnw[t]) + __ldg(&lnb[t]);
    const int b = m >> 12, l = m & 4095;
    const int mo = (b << 12) + __ldg(perm + l);       // original pixel index
    g_g[(size_t)mo * D_INNER + t] = out * g_z[(size_t)mo * D_INNER + t];
}

// ---------------- K6: output GEMM ----------------
__global__ __launch_bounds__(256) void k6_gemm(
    const float* __restrict__ Wout, float* __restrict__ out)
{
    __shared__ float As[16][68];
    __shared__ float Ws[16][68];
    const int n0 = blockIdx.x * 64;
    const int m0 = blockIdx.y * 64;
    const int tid = threadIdx.x;
    const int K = D_INNER;
    const int tx = tid & 15, ty = tid >> 4;
    const int ml = tid >> 2, kl = (tid & 3) * 4;
    float acc[4][4] = {};

    for (int k0 = 0; k0 < K; k0 += 16) {
        float4 a4 = *(const float4*)&g_g [(size_t)(m0 + ml) * K + k0 + kl];
        float4 w4 = *(const float4*)&Wout[(size_t)(n0 + ml) * K + k0 + kl];
        __syncthreads();
        As[kl+0][ml] = a4.x; As[kl+1][ml] = a4.y; As[kl+2][ml] = a4.z; As[kl+3][ml] = a4.w;
        Ws[kl+0][ml] = w4.x; Ws[kl+1][ml] = w4.y; Ws[kl+2][ml] = w4.z; Ws[kl+3][ml] = w4.w;
        __syncthreads();
        #pragma unroll
        for (int kk = 0; kk < 16; kk++) {
            float4 av = *(const float4*)&As[kk][ty*4];
            float4 bv = *(const float4*)&Ws[kk][tx*4];
            float a[4] = {av.x, av.y, av.z, av.w};
            float b[4] = {bv.x, bv.y, bv.z, bv.w};
            #pragma unroll
            for (int i = 0; i < 4; i++)
                #pragma unroll
                for (int j = 0; j < 4; j++)
                    acc[i][j] += a[i] * b[j];
        }
    }
    #pragma unroll
    for (int i = 0; i < 4; i++) {
        int m = m0 + ty*4 + i;
        #pragma unroll
        for (int j = 0; j < 4; j++) {
            int n = n0 + tx*4 + j;
            out[(size_t)m * D_MODEL + n] = acc[i][j];
        }
    }
}

// ---------------- launch ----------------
extern "C" void kernel_launch(void* const* d_in, const int* in_sizes, int n_in,
                              void* d_out, int out_size)
{
    const float* x      = (const float*)d_in[0];
    const float* cond   = (const float*)d_in[1];
    const float* Win    = (const float*)d_in[2];
    const float* Wcon   = (const float*)d_in[3];
    const float* convw  = (const float*)d_in[4];
    const float* convb  = (const float*)d_in[5];
    const float* cconvw = (const float*)d_in[6];
    const float* cconvb = (const float*)d_in[7];
    const float* xpw    = (const float*)d_in[8];
    const float* dtw    = (const float*)d_in[9];
    const float* dtb    = (const float*)d_in[10];
    const float* Alogs  = (const float*)d_in[11];
    const float* DsP    = (const float*)d_in[12];
    const float* lnw    = (const float*)d_in[13];
    const float* lnb    = (const float*)d_in[14];
    const float* Wout   = (const float*)d_in[15];
    const int*   perm   = (const int*)d_in[16];

    k1_gemm<<<dim3(1152/64, MM/64), 256>>>(x, cond, Win, Wcon);
    k2_conv<<<MM/4, 384>>>(convw, convb, cconvw, cconvb);
    k3_proj<<<MM/R3, 384>>>(xpw, dtw, dtb, DsP, perm);
    k4a<<<(NC*D_INNER)/8, 256>>>(Alogs);
    k4b<<<GG/8, 256>>>();
    k4c<<<(NC*D_INNER)/8, 256>>>(Alogs);
    k5_ln<<<MM, 384>>>(lnw, lnb, perm);
    k6_gemm<<<dim3(D_MODEL/64, MM/64), 256>>>(Wout, (float*)d_out);
}

// round 5
// speedup vs baseline: 1.5585x; 1.5585x over previous
#include <cuda_runtime.h>
#include <cstdint>

// Problem constants
#define D_MODEL 192
#define D_INNER 384
#define D_STATE 16
#define DT_RANK 12
#define BB 2
#define HH 64
#define WW 64
#define LL 4096            // HH*WW
#define MM (BB*LL)         // 8192 rows
#define GG (BB*D_INNER)    // 768 sequences
#define NC 32              // chunks per sequence
#define CL (LL/NC)         // 128 steps per chunk

// ---------------- scratch ----------------
__device__ float  g_xa   [MM*D_INNER];
__device__ float  g_z    [MM*D_INNER];
__device__ float  g_c    [MM*D_INNER];
__device__ float  g_u    [MM*D_INNER];
__device__ float  g_s    [MM*D_INNER];
__device__ float2 g_dd   [MM*D_INNER];   // (delta, delta*u) in scan order
__device__ float  g_ud   [MM*D_INNER];   // u*D in scan order
__device__ float  g_bc   [MM*32];        // B(0..15), C(16..31) in scan order
__device__ float  g_y    [MM*D_INNER];   // scan output, SCAN order
__device__ float  g_g    [MM*D_INNER];   // post-LN*z, ORIGINAL order
// chunk summaries
__device__ float g_hF[GG*NC*16];
__device__ float g_P [GG*NC*16];
__device__ float g_hI[GG*NC*16];

__device__ __forceinline__ float silu_f(float x) { return x / (1.f + __expf(-x)); }
__device__ __forceinline__ float softplus_f(float x) {
    return fmaxf(x, 0.f) + log1pf(__expf(-fabsf(x)));
}

// ---------------- K1: fused input GEMMs ----------------
__global__ __launch_bounds__(256) void k1_gemm(
    const float* __restrict__ x, const float* __restrict__ cond,
    const float* __restrict__ Win, const float* __restrict__ Wcon)
{
    __shared__ float As[16][68];
    __shared__ float Ws[16][68];
    const int n0 = blockIdx.x * 64;
    const int m0 = blockIdx.y * 64;
    const int tid = threadIdx.x;
    const bool is_c = (n0 >= 768);
    const float* A = is_c ? cond : x;
    const float* W = is_c ? (Wcon + (size_t)(n0 - 768) * D_MODEL)
                          : (Win  + (size_t)n0 * D_MODEL);
    const int K = D_MODEL;
    const int tx = tid & 15, ty = tid >> 4;
    const int ml = tid >> 2, kl = (tid & 3) * 4;
    float acc[4][4] = {};

    for (int k0 = 0; k0 < K; k0 += 16) {
        float4 a4 = *(const float4*)&A[(size_t)(m0 + ml) * K + k0 + kl];
        float4 w4 = *(const float4*)&W[(size_t)ml * K + k0 + kl];
        __syncthreads();
        As[kl+0][ml] = a4.x; As[kl+1][ml] = a4.y; As[kl+2][ml] = a4.z; As[kl+3][ml] = a4.w;
        Ws[kl+0][ml] = w4.x; Ws[kl+1][ml] = w4.y; Ws[kl+2][ml] = w4.z; Ws[kl+3][ml] = w4.w;
        __syncthreads();
        #pragma unroll
        for (int kk = 0; kk < 16; kk++) {
            float4 av = *(const float4*)&As[kk][ty*4];
            float4 bv = *(const float4*)&Ws[kk][tx*4];
            float a[4] = {av.x, av.y, av.z, av.w};
            float b[4] = {bv.x, bv.y, bv.z, bv.w};
            #pragma unroll
            for (int i = 0; i < 4; i++)
                #pragma unroll
                for (int j = 0; j < 4; j++)
                    acc[i][j] += a[i] * b[j];
        }
    }
    #pragma unroll
    for (int i = 0; i < 4; i++) {
        int m = m0 + ty*4 + i;
        #pragma unroll
        for (int j = 0; j < 4; j++) {
            int n = n0 + tx*4 + j;
            float v = acc[i][j];
            if (n < 384)       g_xa[m*D_INNER + n] = v;
            else if (n < 768)  g_z [m*D_INNER + (n-384)] = silu_f(v);
            else               g_c [m*D_INNER + (n-768)] = v;
        }
    }
}

// ---------------- K2: depthwise 3x3 conv + bias + silu (simple, high-occ) ----------------
__global__ __launch_bounds__(384) void k2_conv(
    const float* __restrict__ cw, const float* __restrict__ cb,
    const float* __restrict__ ccw, const float* __restrict__ ccb)
{
    const int m = blockIdx.x;
    const int d = threadIdx.x;
    const int b = m >> 12, rem = m & 4095, h = rem >> 6, w = rem & 63;
    float ax = 0.f, ac = 0.f;
    #pragma unroll
    for (int dh = -1; dh <= 1; dh++) {
        int h2 = h + dh; if (h2 < 0 || h2 >= HH) continue;
        #pragma unroll
        for (int dw = -1; dw <= 1; dw++) {
            int w2 = w + dw; if (w2 < 0 || w2 >= WW) continue;
            int mi = ((b << 12) + (h2 << 6) + w2) * D_INNER + d;
            int ki = d * 9 + (dh + 1) * 3 + (dw + 1);
            ax += g_xa[mi] * __ldg(&cw[ki]);
            ac += g_c [mi] * __ldg(&ccw[ki]);
        }
    }
    float uv = silu_f(ax + __ldg(&cb[d]));
    float cv = silu_f(ac + __ldg(&ccb[d]));
    g_u[m*D_INNER + d] = uv;
    g_s[m*D_INNER + d] = uv + cv;
}

// ---------------- K3: tiled gather + x_dbl + (delta, delta*u, u*D) + B/C ----------------
#define R3 16
__global__ __launch_bounds__(384) void k3_proj(
    const float* __restrict__ xpw,   // [44,384]
    const float* __restrict__ dtw,   // [384,12]
    const float* __restrict__ dtb,   // [384]
    const float* __restrict__ Ds,    // [384]
    const int*   __restrict__ perm)  // [4096]
{
    __shared__ float sv[R3][D_INNER];
    __shared__ float xd[R3][48];
    __shared__ int   sp[R3];
    const int r0 = blockIdx.x * R3;     // base scan row (over MM)
    const int t = threadIdx.x;

    if (t < R3) sp[t] = __ldg(perm + ((r0 + t) & 4095));
    __syncthreads();

    // stage 1: gather rows of s into smem
    #pragma unroll
    for (int r = 0; r < R3; r++) {
        int ml = r0 + r;
        int b = ml >> 12;
        sv[r][t] = __ldg(&g_s[((size_t)((b << 12) + sp[r])) * D_INNER + t]);
    }
    __syncthreads();

    // stage 2: x_dbl = sv @ xpw^T  -> xd[16][44]
    #pragma unroll
    for (int pass = 0; pass < 2; pass++) {
        int e = t + pass * 384;
        if (e < R3 * 44) {
            int row = e / 44, c = e % 44;
            const float4* wv = (const float4*)(xpw + (size_t)c * D_INNER);
            const float4* s4 = (const float4*)(&sv[row][0]);
            float a = 0.f;
            #pragma unroll
            for (int k = 0; k < D_INNER/4; k++) {
                float4 w4 = __ldg(&wv[k]);
                float4 s_ = s4[k];
                a += w4.x*s_.x + w4.y*s_.y + w4.z*s_.z + w4.w*s_.w;
            }
            xd[row][c] = a;
        }
    }
    __syncthreads();

    // stage 3: delta, delta*u, u*D  (thread t = channel d)
    {
        float wreg[DT_RANK];
        #pragma unroll
        for (int j = 0; j < DT_RANK; j++) wreg[j] = __ldg(&dtw[t * DT_RANK + j]);
        const float bias = __ldg(&dtb[t]);
        const float Dd = __ldg(&Ds[t]);
        #pragma unroll
        for (int r = 0; r < R3; r++) {
            float acc = bias;
            #pragma unroll
            for (int j = 0; j < DT_RANK; j++) acc += xd[r][j] * wreg[j];
            float de = softplus_f(acc);
            int ml = r0 + r;
            int b = ml >> 12;
            float u = __ldg(&g_u[((size_t)((b << 12) + sp[r])) * D_INNER + t]);
            g_dd[(size_t)ml * D_INNER + t] = make_float2(de, de * u);
            g_ud[(size_t)ml * D_INNER + t] = u * Dd;
        }
    }

    // stage 4: B/C out
    for (int idx = t; idx < R3 * 32; idx += 384) {
        int r = idx >> 5, j = idx & 31;
        g_bc[(size_t)(r0 + r) * 32 + j] = xd[r][12 + j];
    }
}

// ---------------- K4a: chunk scan (h0=0), packed: lanes 0-15 = b0, 16-31 = b1 ----------------
__global__ __launch_bounds__(256) void k4a(const float* __restrict__ Alogs)
{
    const int w = blockIdx.x * 8 + (threadIdx.x >> 5);   // w in [0, NC*D_INNER)
    const int lane = threadIdx.x & 31;
    const int chunk = w / D_INNER;
    const int d = w % D_INNER;
    const int half = lane >> 4, sl = lane & 15;
    const float Al = -__expf(__ldg(&Alogs[d * 16 + sl]));

    const int l0 = chunk * CL;
    const size_t rowBase = (size_t)(half * LL + l0);

    float h = 0.f, P = 1.f;
    #pragma unroll 4
    for (int l = 0; l < CL; l++) {
        float2 f = __ldg(&g_dd[(rowBase + l) * D_INNER + d]);
        float Bv = __ldg(&g_bc[(rowBase + l) * 32 + sl]);
        float a  = __expf(f.x * Al);
        h = a * h + f.y * Bv;
        P *= a;
    }
    const int g = half * D_INNER + d;
    g_hF[(g * NC + chunk) * 16 + sl] = h;
    g_P [(g * NC + chunk) * 16 + sl] = P;
}

// ---------------- K4b: serial combine over chunk summaries ----------------
__global__ __launch_bounds__(256) void k4b()
{
    const int g = blockIdx.x * 8 + (threadIdx.x >> 5);
    const int lane = threadIdx.x & 31;
    if (lane < 16) {
        float h = 0.f;
        #pragma unroll
        for (int c = 0; c < NC; c++) {
            int i = (g * NC + c) * 16 + lane;
            g_hI[i] = h;
            h = g_P[i] * h + g_hF[i];
        }
    }
}

// ---------------- K4c: final chunk scan, packed halves, y in scan order ----------------
__global__ __launch_bounds__(256) void k4c(const float* __restrict__ Alogs)
{
    const int w = blockIdx.x * 8 + (threadIdx.x >> 5);
    const int lane = threadIdx.x & 31;
    const int chunk = w / D_INNER;
    const int d = w % D_INNER;
    const int half = lane >> 4, sl = lane & 15;
    const float Al = -__expf(__ldg(&Alogs[d * 16 + sl]));

    const int l0 = chunk * CL;
    const size_t rowBase = (size_t)(half * LL + l0);
    const int g = half * D_INNER + d;

    float h = g_hI[(g * NC + chunk) * 16 + sl];

    for (int l4 = 0; l4 < CL; l4 += 4) {
        float pr[4], ud[4];
        #pragma unroll
        for (int j = 0; j < 4; j++) {
            int l = l4 + j;
            float2 f = __ldg(&g_dd[(rowBase + l) * D_INNER + d]);
            float Bv = __ldg(&g_bc[(rowBase + l) * 32 + sl]);
            float Cv = __ldg(&g_bc[(rowBase + l) * 32 + 16 + sl]);
            float a  = __expf(f.x * Al);
            h = a * h + f.y * Bv;
            pr[j] = h * Cv;
            ud[j] = __ldg(&g_ud[(rowBase + l) * D_INNER + d]);
        }
        #pragma unroll
        for (int j = 0; j < 4; j++) {
            float s = pr[j];
            s += __shfl_xor_sync(0xffffffffu, s, 8);
            s += __shfl_xor_sync(0xffffffffu, s, 4);
            s += __shfl_xor_sync(0xffffffffu, s, 2);
            s += __shfl_xor_sync(0xffffffffu, s, 1);
            if (sl == 0)
                g_y[(rowBase + l4 + j) * D_INNER + d] = s + ud[j];
        }
    }
}

// ---------------- K5: LayerNorm (scan order in) * silu(z), un-permute on write ----------------
__global__ __launch_bounds__(384) void k5_ln(
    const float* __restrict__ lnw, const float* __restrict__ lnb,
    const int* __restrict__ perm)
{
    __shared__ float red0[12], red1[12];
    const int m = blockIdx.x, t = threadIdx.x;   // m = scan row (b*LL + l)
    float v = g_y[(size_t)m * D_INNER + t];
    float s = v, s2 = v * v;
    #pragma unroll
    for (int o = 16; o; o >>= 1) {
        s  += __shfl_xor_sync(0xffffffffu, s,  o);
        s2 += __shfl_xor_sync(0xffffffffu, s2, o);
    }
    if ((t & 31) == 0) { red0[t >> 5] = s; red1[t >> 5] = s2; }
    __syncthreads();
    if (t < 32) {
        float a = (t < 12) ? red0[t] : 0.f;
        float c = (t < 12) ? red1[t] : 0.f;
        #pragma unroll
        for (int o = 16; o; o >>= 1) {
            a += __shfl_xor_sync(0xffffffffu, a, o);
            c += __shfl_xor_sync(0xffffffffu, c, o);
        }
        if (t == 0) { red0[0] = a; red1[0] = c; }
    }
    __syncthreads();
    const float mu  = red0[0] * (1.f / D_INNER);
    const float var = red1[0] * (1.f / D_INNER) - mu * mu;
    const float r = rsqrtf(var + 1e-5f);
    float out = (v - mu) * r * __ldg(&lnw[t]) + __ldg(&lnb[t]);
    const int b = m >> 12, l = m & 4095;
    const int mo = (b << 12) + __ldg(perm + l);       // original pixel index
    g_g[(size_t)mo * D_INNER + t] = out * g_z[(size_t)mo * D_INNER + t];
}

// ---------------- K6: output GEMM ----------------
__global__ __launch_bounds__(256) void k6_gemm(
    const float* __restrict__ Wout, float* __restrict__ out)
{
    __shared__ float As[16][68];
    __shared__ float Ws[16][68];
    const int n0 = blockIdx.x * 64;
    const int m0 = blockIdx.y * 64;
    const int tid = threadIdx.x;
    const int K = D_INNER;
    const int tx = tid & 15, ty = tid >> 4;
    const int ml = tid >> 2, kl = (tid & 3) * 4;
    float acc[4][4] = {};

    for (int k0 = 0; k0 < K; k0 += 16) {
        float4 a4 = *(const float4*)&g_g [(size_t)(m0 + ml) * K + k0 + kl];
        float4 w4 = *(const float4*)&Wout[(size_t)(n0 + ml) * K + k0 + kl];
        __syncthreads();
        As[kl+0][ml] = a4.x; As[kl+1][ml] = a4.y; As[kl+2][ml] = a4.z; As[kl+3][ml] = a4.w;
        Ws[kl+0][ml] = w4.x; Ws[kl+1][ml] = w4.y; Ws[kl+2][ml] = w4.z; Ws[kl+3][ml] = w4.w;
        __syncthreads();
        #pragma unroll
        for (int kk = 0; kk < 16; kk++) {
            float4 av = *(const float4*)&As[kk][ty*4];
            float4 bv = *(const float4*)&Ws[kk][tx*4];
            float a[4] = {av.x, av.y, av.z, av.w};
            float b[4] = {bv.x, bv.y, bv.z, bv.w};
            #pragma unroll
            for (int i = 0; i < 4; i++)
                #pragma unroll
                for (int j = 0; j < 4; j++)
                    acc[i][j] += a[i] * b[j];
        }
    }
    #pragma unroll
    for (int i = 0; i < 4; i++) {
        int m = m0 + ty*4 + i;
        #pragma unroll
        for (int j = 0; j < 4; j++) {
            int n = n0 + tx*4 + j;
            out[(size_t)m * D_MODEL + n] = acc[i][j];
        }
    }
}

// ---------------- launch ----------------
extern "C" void kernel_launch(void* const* d_in, const int* in_sizes, int n_in,
                              void* d_out, int out_size)
{
    const float* x      = (const float*)d_in[0];
    const float* cond   = (const float*)d_in[1];
    const float* Win    = (const float*)d_in[2];
    const float* Wcon   = (const float*)d_in[3];
    const float* convw  = (const float*)d_in[4];
    const float* convb  = (const float*)d_in[5];
    const float* cconvw = (const float*)d_in[6];
    const float* cconvb = (const float*)d_in[7];
    const float* xpw    = (const float*)d_in[8];
    const float* dtw    = (const float*)d_in[9];
    const float* dtb    = (const float*)d_in[10];
    const float* Alogs  = (const float*)d_in[11];
    const float* DsP    = (const float*)d_in[12];
    const float* lnw    = (const float*)d_in[13];
    const float* lnb    = (const float*)d_in[14];
    const float* Wout   = (const float*)d_in[15];
    const int*   perm   = (const int*)d_in[16];

    k1_gemm<<<dim3(1152/64, MM/64), 256>>>(x, cond, Win, Wcon);
    k2_conv<<<MM, 384>>>(convw, convb, cconvw, cconvb);
    k3_proj<<<MM/R3, 384>>>(xpw, dtw, dtb, DsP, perm);
    k4a<<<(NC*D_INNER)/8, 256>>>(Alogs);
    k4b<<<GG/8, 256>>>();
    k4c<<<(NC*D_INNER)/8, 256>>>(Alogs);
    k5_ln<<<MM, 384>>>(lnw, lnb, perm);
    k6_gemm<<<dim3(D_MODEL/64, MM/64), 256>>>(Wout, (float*)d_out);
}